// round 4
// baseline (speedup 1.0000x reference)
#include <cuda_runtime.h>
#include <cstdint>
#include <math.h>

#define NTOK 16384
#define DIM  1024
#define NE   8
#define CAP  2560          // int(1.25 * 16384 / 8)
#define BK   32
#define NCH  (DIM / BK)

// ---------------- device scratch (no allocation allowed) -------------------
__device__ int   g_top[NTOK * 2];
__device__ float g_gate[NTOK * 2];
__device__ int   g_slot[NTOK * 2];        // slot within expert, -1 if dropped
__device__ int   g_row_token[NE * CAP];
__device__ int   g_load[NE];
__device__ float g_H[(size_t)NE * CAP * DIM];   // hidden activations (84 MB)
__device__ float g_O[(size_t)NE * CAP * DIM];   // expert outputs + b2 (84 MB)

// ---------------- helpers ---------------------------------------------------
__device__ __forceinline__ uint32_t smem_u32(const void* p) {
    uint32_t a;
    asm("{ .reg .u64 t; cvta.to.shared.u64 t, %1; cvt.u32.u64 %0, t; }"
        : "=r"(a) : "l"(p));
    return a;
}

// split 8 fp32 -> 8 bf16 hi (uint4) + 8 bf16 lo (uint4)
__device__ __forceinline__ void split8(const float4 f0, const float4 f1,
                                       uint4& hi, uint4& lo) {
    const float f[8] = {f0.x, f0.y, f0.z, f0.w, f1.x, f1.y, f1.z, f1.w};
    uint32_t h[4], l[4];
#pragma unroll
    for (int i = 0; i < 4; i++) {
        float a = f[2 * i], b = f[2 * i + 1];
        uint32_t hp;
        asm("cvt.rn.bf16x2.f32 %0, %1, %2;" : "=r"(hp) : "f"(b), "f"(a));
        float ra = a - __uint_as_float(hp << 16);
        float rb = b - __uint_as_float(hp & 0xFFFF0000u);
        uint32_t lp;
        asm("cvt.rn.bf16x2.f32 %0, %1, %2;" : "=r"(lp) : "f"(rb), "f"(ra));
        h[i] = hp; l[i] = lp;
    }
    hi = make_uint4(h[0], h[1], h[2], h[3]);
    lo = make_uint4(l[0], l[1], l[2], l[3]);
}

__device__ __forceinline__ void ldsm4(uint32_t* r, uint32_t addr) {
    asm volatile("ldmatrix.sync.aligned.m8n8.x4.shared.b16 {%0,%1,%2,%3}, [%4];"
                 : "=r"(r[0]), "=r"(r[1]), "=r"(r[2]), "=r"(r[3]) : "r"(addr));
}
__device__ __forceinline__ void mma_bf16(float* d, const uint32_t* a,
                                         const uint32_t* b) {
    asm volatile(
        "mma.sync.aligned.m16n8k16.row.col.f32.bf16.bf16.f32 "
        "{%0,%1,%2,%3}, {%4,%5,%6,%7}, {%8,%9}, {%0,%1,%2,%3};"
        : "+f"(d[0]), "+f"(d[1]), "+f"(d[2]), "+f"(d[3])
        : "r"(a[0]), "r"(a[1]), "r"(a[2]), "r"(a[3]), "r"(b[0]), "r"(b[1]));
}

// SMEM: [0..512) row indices; stage s at 512 + s*32768:
//   A tile 16KB (128 rows x 128B: chunks 0-3 = hi k0..31, 4-7 = lo),
//   B tile 16KB at +16384. Swizzle: 16B chunk c of row r at ((c ^ (r&7))*16).
#define STAGE_B  32768
#define SMEM_DYN (512 + 2 * STAGE_B)

// ---------------- tensor-core (HMMA) GEMM, both layers ---------------------
// C[128x128] = A[128x1024] @ W[e][128x1024]^T  (+bias, relu for G1)
// 3-term bf16 split: Ah*Bh + Ah*Bl + Al*Bh, fp32 accumulate.
template <bool G2>
__global__ void __launch_bounds__(256)
moe_gemm(const float* __restrict__ Asrc, const float* __restrict__ Wsrc,
         const float* __restrict__ bias) {
    extern __shared__ __align__(16) char dsm[];
    int* rows = (int*)dsm;

    const int e = blockIdx.z;
    const int loadE = g_load[e];
    const int m0 = blockIdx.y * 128;
    if (m0 >= loadE) return;
    const int n0 = blockIdx.x * 128;
    const int tid = threadIdx.x;
    const int lane = tid & 31, wid = tid >> 5;
    const int wm = wid >> 2, wn = wid & 3;     // warp tile: 64 rows x 32 cols
    const uint32_t sb = smem_u32(dsm);

    if (!G2 && tid < 128) {
        int m = m0 + tid;
        rows[tid] = g_row_token[e * CAP + (m < loadE ? m : loadE - 1)];
    }
    __syncthreads();

    // global load assignment: thread -> (row r, half j of 32-float chunk)
    const int r = tid >> 1;
    const int j = tid & 1;
    const float* pa = (G2 ? (g_H + ((size_t)e * CAP + m0 + r) * DIM)
                          : (Asrc + (size_t)rows[r] * DIM)) + j * 16;
    const float* pb = Wsrc + ((size_t)e * DIM + n0 + r) * DIM + j * 16;

    float4 fa[4], fb[4];
    float acc[4][4][4];
#pragma unroll
    for (int i = 0; i < 4; i++)
#pragma unroll
        for (int jj = 0; jj < 4; jj++)
#pragma unroll
            for (int k = 0; k < 4; k++) acc[i][jj][k] = 0.f;

    auto ldglobal = [&](int c) {
        const float4* qa = (const float4*)(pa + c * BK);
        const float4* qb = (const float4*)(pb + c * BK);
#pragma unroll
        for (int i = 0; i < 4; i++) { fa[i] = __ldg(qa + i); fb[i] = __ldg(qb + i); }
    };

    // conflict-free split+store: r-dependent chunk order, SW128 swizzle
    const int rp = (r >> 1) & 1;
    const int sw = r & 7;
    const int jx = j ? 6 : 0;
    auto stchunk = [&](int stg) {
        char* Ab = dsm + 512 + stg * STAGE_B;
        char* Bb = Ab + 16384;
        uint4 va[4], vb[4];
        split8(fa[0], fa[1], va[0], va[2]);
        split8(fa[2], fa[3], va[1], va[3]);
        split8(fb[0], fb[1], vb[0], vb[2]);
        split8(fb[2], fb[3], vb[1], vb[3]);
#pragma unroll
        for (int k = 0; k < 4; k++) {
            int c = (4 * (k >> 1) + ((k & 1) ^ rp)) ^ jx;
            int li = ((c >> 2) << 1) | (c & 1);
            uint32_t off = (uint32_t)r * 128 + (uint32_t)((c ^ sw) << 4);
            *(uint4*)(Ab + off) = va[li];
            *(uint4*)(Bb + off) = vb[li];
        }
    };

    // fragment row/addr precompute
    uint32_t aoff[4], boff[2];
#pragma unroll
    for (int ms = 0; ms < 4; ms++) {
        uint32_t row = wm * 64 + ms * 16 + (lane & 15);
        aoff[ms] = row * 128 + (((lane >> 4) ^ (row & 7)) << 4);
    }
#pragma unroll
    for (int np = 0; np < 2; np++) {
        uint32_t row = wn * 32 + np * 16 + (lane & 7) + ((lane >> 4) & 1) * 8;
        boff[np] = row * 128 + ((((lane >> 3) & 1) ^ (row & 7)) << 4);
    }

    auto compute = [&](int stg) {
        const uint32_t Ab = sb + 512 + stg * STAGE_B;
        const uint32_t Bb = Ab + 16384;
#pragma unroll
        for (int s = 0; s < 2; s++) {
            uint32_t ah[4][4], al[4][4], bh[4][2], bl[4][2];
            // swizzle-aware chunk advance: chunk c -> c^s' pattern via xor on addr
            const uint32_t sx = (uint32_t)(2 * s) << 4;   // +2 chunks == xor (2s)<<4
            const uint32_t lx = 4u << 4;                  // +4 chunks == xor 4<<4
#pragma unroll
            for (int ms = 0; ms < 4; ms++) {
                ldsm4(ah[ms], Ab + (aoff[ms] ^ sx));
                ldsm4(al[ms], Ab + (aoff[ms] ^ sx ^ lx));
            }
#pragma unroll
            for (int np = 0; np < 2; np++) {
                uint32_t t[4];
                ldsm4(t, Bb + (boff[np] ^ sx));
                bh[2 * np][0] = t[0]; bh[2 * np][1] = t[1];
                bh[2 * np + 1][0] = t[2]; bh[2 * np + 1][1] = t[3];
                ldsm4(t, Bb + (boff[np] ^ sx ^ lx));
                bl[2 * np][0] = t[0]; bl[2 * np][1] = t[1];
                bl[2 * np + 1][0] = t[2]; bl[2 * np + 1][1] = t[3];
            }
#pragma unroll
            for (int ms = 0; ms < 4; ms++)
#pragma unroll
                for (int ns = 0; ns < 4; ns++) {
                    mma_bf16(acc[ms][ns], ah[ms], bh[ns]);
                    mma_bf16(acc[ms][ns], ah[ms], bl[ns]);
                    mma_bf16(acc[ms][ns], al[ms], bh[ns]);
                }
        }
    };

    ldglobal(0);
    stchunk(0);
    ldglobal(1);
    __syncthreads();
#pragma unroll 1
    for (int c = 0; c < NCH; c++) {
        if (c + 1 < NCH) stchunk((c + 1) & 1);   // writes other stage
        if (c + 2 < NCH) ldglobal(c + 2);
        compute(c & 1);
        __syncthreads();
    }

    // epilogue
    const float* bE = bias + e * DIM;
    float* dst = (G2 ? g_O : g_H);
#pragma unroll
    for (int ms = 0; ms < 4; ms++) {
        const int row = m0 + wm * 64 + ms * 16 + (lane >> 2);
#pragma unroll
        for (int ns = 0; ns < 4; ns++) {
            const int col = n0 + wn * 32 + ns * 8 + 2 * (lane & 3);
            const float2 bv = *(const float2*)(bE + col);
            float2 v0, v1;
            v0.x = acc[ms][ns][0] + bv.x; v0.y = acc[ms][ns][1] + bv.y;
            v1.x = acc[ms][ns][2] + bv.x; v1.y = acc[ms][ns][3] + bv.y;
            if (!G2) {
                v0.x = v0.x > 0.f ? v0.x : 0.f; v0.y = v0.y > 0.f ? v0.y : 0.f;
                v1.x = v1.x > 0.f ? v1.x : 0.f; v1.y = v1.y > 0.f ? v1.y : 0.f;
            }
            float* p0 = dst + ((size_t)e * CAP + row) * DIM + col;
            *(float2*)p0 = v0;
            *(float2*)(p0 + 8 * DIM) = v1;
        }
    }
}

// ---------------- router ---------------------------------------------------
__global__ void router_kernel(const float* __restrict__ x,
                              const float* __restrict__ Wr,
                              const float* __restrict__ br) {
    int token = (blockIdx.x * blockDim.x + threadIdx.x) >> 5;
    int lane  = threadIdx.x & 31;
    if (token >= NTOK) return;
    const float* xr = x + (size_t)token * DIM;
    float acc[NE];
#pragma unroll
    for (int e = 0; e < NE; e++) acc[e] = 0.f;
    for (int d = lane; d < DIM; d += 32) {
        float xv = xr[d];
#pragma unroll
        for (int e = 0; e < NE; e++) acc[e] += xv * Wr[e * DIM + d];
    }
#pragma unroll
    for (int e = 0; e < NE; e++)
#pragma unroll
        for (int o = 16; o; o >>= 1)
            acc[e] += __shfl_xor_sync(0xffffffffu, acc[e], o);
    if (lane == 0) {
        float l[NE];
#pragma unroll
        for (int e = 0; e < NE; e++) l[e] = acc[e] + br[e];
        float v1 = -3.4e38f; int i1 = 0;
#pragma unroll
        for (int e = 0; e < NE; e++) if (l[e] > v1) { v1 = l[e]; i1 = e; }
        float v2 = -3.4e38f; int i2 = 0;
#pragma unroll
        for (int e = 0; e < NE; e++) if (e != i1 && l[e] > v2) { v2 = l[e]; i2 = e; }
        float ex = expf(v2 - v1);
        float inv = 1.f / (1.f + ex);
        g_top[2 * token]      = i1;
        g_top[2 * token + 1]  = i2;
        g_gate[2 * token]     = inv;
        g_gate[2 * token + 1] = ex * inv;
    }
}

// ---------------- dispatch scan --------------------------------------------
__global__ void scan_kernel() {
    int e = blockIdx.x;
    __shared__ int wsum[32];
    __shared__ int total_s;
    int lane = threadIdx.x & 31;
    int wid  = threadIdx.x >> 5;
    int running = 0;
    for (int base = 0; base < NTOK; base += 1024) {
        int n = base + threadIdx.x;
        int k = -1;
        int t0 = g_top[2 * n], t1 = g_top[2 * n + 1];
        if (t0 == e) k = 0; else if (t1 == e) k = 1;
        unsigned b = __ballot_sync(0xffffffffu, k >= 0);
        int pw = __popc(b & ((1u << lane) - 1u));
        if (lane == 0) wsum[wid] = __popc(b);
        __syncthreads();
        if (wid == 0) {
            int v = wsum[lane];
            int s = v;
#pragma unroll
            for (int o = 1; o < 32; o <<= 1) {
                int u = __shfl_up_sync(0xffffffffu, s, o);
                if (lane >= o) s += u;
            }
            wsum[lane] = s - v;
            if (lane == 31) total_s = s;
        }
        __syncthreads();
        if (k >= 0) {
            int pos = running + wsum[wid] + pw;
            if (pos < CAP) {
                g_row_token[e * CAP + pos] = n;
                g_slot[2 * n + k] = pos;
            } else {
                g_slot[2 * n + k] = -1;
            }
        }
        running += total_s;
        __syncthreads();
    }
    if (threadIdx.x == 0) g_load[e] = running < CAP ? running : CAP;
}

// ---------------- combine: out[t] = sum_k gate * O[e_k, slot_k] ------------
__global__ void combine_kernel(float* __restrict__ out) {
    int t = blockIdx.x * 8 + (threadIdx.x >> 5);
    int lane = threadIdx.x & 31;
    float4 acc[8];
#pragma unroll
    for (int i = 0; i < 8; i++) acc[i] = make_float4(0.f, 0.f, 0.f, 0.f);
#pragma unroll
    for (int k = 0; k < 2; k++) {
        int s = g_slot[2 * t + k];
        if (s >= 0) {
            int e = g_top[2 * t + k];
            float g = g_gate[2 * t + k];
            const float4* p = (const float4*)(g_O + ((size_t)e * CAP + s) * DIM);
#pragma unroll
            for (int i = 0; i < 8; i++) {
                float4 v = __ldg(p + lane + i * 32);
                acc[i].x += g * v.x; acc[i].y += g * v.y;
                acc[i].z += g * v.z; acc[i].w += g * v.w;
            }
        }
    }
    float4* o = (float4*)(out + (size_t)t * DIM);
#pragma unroll
    for (int i = 0; i < 8; i++) o[lane + i * 32] = acc[i];
}

// ---------------- stats -----------------------------------------------------
__global__ void stats_kernel(float* __restrict__ out) {
    if (threadIdx.x == 0) {
        float l[NE], s = 0.f;
#pragma unroll
        for (int e = 0; e < NE; e++) { l[e] = (float)g_load[e]; s += l[e]; }
        float inv = 1.f / (s + 1e-8f);
        float loss = 0.f;
#pragma unroll
        for (int e = 0; e < NE; e++) {
            float d = l[e] * inv;
            out[(size_t)NTOK * DIM + 1 + e] = d;
            loss -= d * logf(d + 1e-8f);
        }
        out[(size_t)NTOK * DIM] = loss;
    }
}

// ---------------- launch ----------------------------------------------------
extern "C" void kernel_launch(void* const* d_in, const int* in_sizes, int n_in,
                              void* d_out, int out_size) {
    const float* x  = (const float*)d_in[0];
    const float* Wr = (const float*)d_in[1];
    const float* br = (const float*)d_in[2];
    const float* W1 = (const float*)d_in[3];
    const float* b1 = (const float*)d_in[4];
    const float* W2 = (const float*)d_in[5];
    const float* b2 = (const float*)d_in[6];
    float* out = (float*)d_out;

    cudaFuncSetAttribute(moe_gemm<false>,
                         cudaFuncAttributeMaxDynamicSharedMemorySize, SMEM_DYN);
    cudaFuncSetAttribute(moe_gemm<true>,
                         cudaFuncAttributeMaxDynamicSharedMemorySize, SMEM_DYN);

    router_kernel<<<NTOK / 8, 256>>>(x, Wr, br);
    scan_kernel<<<NE, 1024>>>();
    dim3 grid(DIM / 128, CAP / 128, NE);
    moe_gemm<false><<<grid, 256, SMEM_DYN>>>(x, W1, b1);
    moe_gemm<true><<<grid, 256, SMEM_DYN>>>(x, W2, b2);
    combine_kernel<<<NTOK / 8, 256>>>(out);
    stats_kernel<<<1, 32>>>(out);
}